// round 1
// baseline (speedup 1.0000x reference)
#include <cuda_runtime.h>
#include <math.h>

#define NAA 4096
#define DAA 128
#define DMM 512
#define PPP 32768
#define WIN 16
#define BAND 33

// ---------------- scratch (device globals; no allocation) ----------------
__device__ float d_cond  [NAA * DAA];
__device__ float d_ad    [NAA * 512];     // [g1|b1|g2|b2] per row
__device__ float d_qn    [NAA * DAA];
__device__ float d_qkvg  [NAA * 512];     // [Q|K|V|G] per row
__device__ float d_gates [NAA * 256];     // sigmoided [gate1|gate2]
__device__ float d_attout[NAA * DAA];
__device__ float d_womul [NAA * DAA];
__device__ float d_q1    [NAA * DAA];
__device__ float d_qn2   [NAA * DAA];
__device__ float d_ff    [NAA * 1024];    // [h1|h3]
__device__ float d_hid   [NAA * 512];
__device__ float d_swi   [NAA * DAA];
__device__ int   d_bandp [NAA * BAND];
__device__ float d_Wqkvg [DAA * 512];
__device__ float d_Wad   [DAA * 512];
__device__ float d_Bad   [512];
__device__ float d_Wg    [DAA * 256];
__device__ float d_Bg    [256];
__device__ float d_Wff   [DAA * 1024];

// ---------------- generic fp32 tiled GEMM: C = A[MxK] @ B[KxN] ----------------
#define BM 64
#define BN 64
#define BK 16

__global__ void gemm_kernel(const float* __restrict__ A, const float* __restrict__ B,
                            const float* __restrict__ bias, float* __restrict__ C,
                            int M, int N, int K, int epi) {
    __shared__ float As[BK][BM + 4];
    __shared__ float Bs[BK][BN + 4];
    const int tid = threadIdx.x;                 // 256 threads
    const int tx = tid & 15, ty = tid >> 4;
    const int row0 = blockIdx.y * BM, col0 = blockIdx.x * BN;
    const int ar = tid >> 2, aq = tid & 3;       // A tile: 64 rows x 16 cols (float4)
    const int br = tid >> 4, bq = tid & 15;      // B tile: 16 rows x 64 cols (float4)
    float acc[4][4] = {};
    const float* Aptr = A + (size_t)(row0 + ar) * K + aq * 4;
    const float* Bptr = B + (size_t)br * N + col0 + bq * 4;

    for (int k0 = 0; k0 < K; k0 += BK) {
        float4 av = *(const float4*)(Aptr + k0);
        float4 bv = *(const float4*)(Bptr + (size_t)k0 * N);
        As[aq * 4 + 0][ar] = av.x;
        As[aq * 4 + 1][ar] = av.y;
        As[aq * 4 + 2][ar] = av.z;
        As[aq * 4 + 3][ar] = av.w;
        *(float4*)&Bs[br][bq * 4] = bv;
        __syncthreads();
#pragma unroll
        for (int k = 0; k < BK; k++) {
            float a0 = As[k][ty * 4 + 0], a1 = As[k][ty * 4 + 1];
            float a2 = As[k][ty * 4 + 2], a3 = As[k][ty * 4 + 3];
            float4 b = *(const float4*)&Bs[k][tx * 4];
            acc[0][0] += a0 * b.x; acc[0][1] += a0 * b.y; acc[0][2] += a0 * b.z; acc[0][3] += a0 * b.w;
            acc[1][0] += a1 * b.x; acc[1][1] += a1 * b.y; acc[1][2] += a1 * b.z; acc[1][3] += a1 * b.w;
            acc[2][0] += a2 * b.x; acc[2][1] += a2 * b.y; acc[2][2] += a2 * b.z; acc[2][3] += a2 * b.w;
            acc[3][0] += a3 * b.x; acc[3][1] += a3 * b.y; acc[3][2] += a3 * b.z; acc[3][3] += a3 * b.w;
        }
        __syncthreads();
    }
#pragma unroll
    for (int i = 0; i < 4; i++) {
        int r = row0 + ty * 4 + i;
#pragma unroll
        for (int j = 0; j < 4; j++) {
            int c = col0 + tx * 4 + j;
            float v = acc[i][j];
            if (epi >= 1) v += bias[c];
            if (epi == 2) v = 1.f / (1.f + expf(-v));
            C[(size_t)r * N + c] = v;
        }
    }
}

// cond = gather(h_cond, token_idx) @ cond_proj_w + cond_proj_b + t_emb
// M=NAA, K=DMM=512, N=DAA=128
__global__ void gemm_cond_kernel(const float* __restrict__ Hc, const int* __restrict__ tok,
                                 const float* __restrict__ B, const float* __restrict__ bias,
                                 const float* __restrict__ temb, float* __restrict__ C) {
    __shared__ float As[BK][BM + 4];
    __shared__ float Bs[BK][BN + 4];
    const int tid = threadIdx.x;
    const int tx = tid & 15, ty = tid >> 4;
    const int row0 = blockIdx.y * BM, col0 = blockIdx.x * BN;
    const int ar = tid >> 2, aq = tid & 3;
    const int br = tid >> 4, bq = tid & 15;
    float acc[4][4] = {};
    const int arow = tok[row0 + ar];
    const float* Aptr = Hc + (size_t)arow * DMM + aq * 4;
    const float* Bptr = B + (size_t)br * DAA + col0 + bq * 4;

    for (int k0 = 0; k0 < DMM; k0 += BK) {
        float4 av = *(const float4*)(Aptr + k0);
        float4 bv = *(const float4*)(Bptr + (size_t)k0 * DAA);
        As[aq * 4 + 0][ar] = av.x;
        As[aq * 4 + 1][ar] = av.y;
        As[aq * 4 + 2][ar] = av.z;
        As[aq * 4 + 3][ar] = av.w;
        *(float4*)&Bs[br][bq * 4] = bv;
        __syncthreads();
#pragma unroll
        for (int k = 0; k < BK; k++) {
            float a0 = As[k][ty * 4 + 0], a1 = As[k][ty * 4 + 1];
            float a2 = As[k][ty * 4 + 2], a3 = As[k][ty * 4 + 3];
            float4 b = *(const float4*)&Bs[k][tx * 4];
            acc[0][0] += a0 * b.x; acc[0][1] += a0 * b.y; acc[0][2] += a0 * b.z; acc[0][3] += a0 * b.w;
            acc[1][0] += a1 * b.x; acc[1][1] += a1 * b.y; acc[1][2] += a1 * b.z; acc[1][3] += a1 * b.w;
            acc[2][0] += a2 * b.x; acc[2][1] += a2 * b.y; acc[2][2] += a2 * b.z; acc[2][3] += a2 * b.w;
            acc[3][0] += a3 * b.x; acc[3][1] += a3 * b.y; acc[3][2] += a3 * b.z; acc[3][3] += a3 * b.w;
        }
        __syncthreads();
    }
#pragma unroll
    for (int i = 0; i < 4; i++) {
        int r = row0 + ty * 4 + i;
#pragma unroll
        for (int j = 0; j < 4; j++) {
            int c = col0 + tx * 4 + j;
            C[(size_t)r * DAA + c] = acc[i][j] + bias[c] + temb[c];
        }
    }
}

// ---------------- weight packing ----------------
__global__ void pack_qkvg_kernel(const float* __restrict__ wq, const float* __restrict__ wk,
                                 const float* __restrict__ wv, const float* __restrict__ wg,
                                 float* __restrict__ W) {
    int idx = blockIdx.x * blockDim.x + threadIdx.x;
    if (idx >= DAA * DAA) return;
    int r = idx >> 7, c = idx & 127;
    float* d = W + (size_t)r * 512;
    d[c] = wq[idx]; d[128 + c] = wk[idx]; d[256 + c] = wv[idx]; d[384 + c] = wg[idx];
}

__global__ void pack2_kernel(const float* __restrict__ a, const float* __restrict__ b,
                             float* __restrict__ W, int rows, int cols) {
    int idx = blockIdx.x * blockDim.x + threadIdx.x;
    if (idx >= rows * cols) return;
    int r = idx / cols, c = idx % cols;
    W[(size_t)r * 2 * cols + c] = a[idx];
    W[(size_t)r * 2 * cols + cols + c] = b[idx];
}

__global__ void packv2_kernel(const float* __restrict__ a, const float* __restrict__ b,
                              float* __restrict__ v, int n) {
    int i = blockIdx.x * blockDim.x + threadIdx.x;
    if (i >= n) return;
    v[i] = a[i]; v[n + i] = b[i];
}

// ---------------- LayerNorm + AdaLN modulation ----------------
// out = (1 + g) * LN(x)[*lng + lnb] + b ; g = ad[row*512+gcol+c], b = ad[row*512+gcol+128+c]
__global__ void ln_mod_kernel(const float* __restrict__ x, const float* __restrict__ ad,
                              int gcol, const float* __restrict__ lng,
                              const float* __restrict__ lnb, float* __restrict__ out) {
    int row = blockIdx.x * 8 + (threadIdx.x >> 5);
    int lane = threadIdx.x & 31;
    const float* xr = x + (size_t)row * DAA;
    float4 v = *(const float4*)(xr + lane * 4);
    float s = v.x + v.y + v.z + v.w;
    float sq = v.x * v.x + v.y * v.y + v.z * v.z + v.w * v.w;
#pragma unroll
    for (int o = 16; o; o >>= 1) {
        s  += __shfl_xor_sync(0xffffffffu, s, o);
        sq += __shfl_xor_sync(0xffffffffu, sq, o);
    }
    float m = s * (1.f / 128.f);
    float var = sq * (1.f / 128.f) - m * m;
    float rstd = rsqrtf(var + 1e-5f);
    const float* adr = ad + (size_t)row * 512 + gcol;
    float xv[4] = {v.x, v.y, v.z, v.w};
#pragma unroll
    for (int u = 0; u < 4; u++) {
        int c = lane * 4 + u;
        float n = (xv[u] - m) * rstd;
        if (lng) n = n * lng[c] + lnb[c];
        out[(size_t)row * DAA + c] = (1.f + adr[c]) * n + adr[128 + c];
    }
}

// ---------------- pair bias band scatter ----------------
__global__ void band_init_kernel(int* __restrict__ bp) {
    int i = blockIdx.x * blockDim.x + threadIdx.x;
    if (i < NAA * BAND) bp[i] = -1;
}

__global__ void scatter_pairs_kernel(const int* __restrict__ p_lm_idx, int* __restrict__ bp) {
    int p = blockIdx.x * blockDim.x + threadIdx.x;
    if (p >= PPP) return;
    int i = p_lm_idx[2 * p], j = p_lm_idx[2 * p + 1];
    int dlt = j - i;
    if (dlt >= -WIN && dlt <= WIN) atomicMax(&bp[i * BAND + dlt + WIN], p);
}

// ---------------- banded attention ----------------
__global__ void attn_kernel(const float* __restrict__ QKVG, const int* __restrict__ bp,
                            const float* __restrict__ p_lm, const float* __restrict__ pair_w,
                            const float* __restrict__ pair_b, float* __restrict__ attout) {
    __shared__ float Kb[BAND][DAA];
    __shared__ float Vb[BAND][DAA];
    __shared__ float qv[DAA];
    __shared__ float sc[4][BAND];
    const int i = blockIdx.x;
    const int tid = threadIdx.x;                 // 128 threads
    const int jlo = (i - WIN) > 0 ? (i - WIN) : 0;
    const int jhi = (i + WIN) < (NAA - 1) ? (i + WIN) : (NAA - 1);
    const int cnt = jhi - jlo + 1;

    qv[tid] = QKVG[(size_t)i * 512 + tid];
    for (int idx = tid; idx < cnt * DAA; idx += 128) {
        int r = idx >> 7, c = idx & 127;
        const float* src = QKVG + (size_t)(jlo + r) * 512;
        Kb[r][c] = src[128 + c];
        Vb[r][c] = src[256 + c];
    }
    __syncthreads();

    for (int s = tid; s < 4 * cnt; s += 128) {
        int h = s & 3, jj = s >> 2;
        float acc = 0.f;
#pragma unroll
        for (int d = 0; d < 32; d++) acc += qv[h * 32 + d] * Kb[jj][h * 32 + d];
        acc *= 0.17677669529663687f;   // 1/sqrt(32)
        int p = bp[i * BAND + (jlo + jj) - i + WIN];
        if (p >= 0) {
            float bs = pair_b[h];
#pragma unroll
            for (int t = 0; t < 16; t++) bs += p_lm[p * 16 + t] * pair_w[t * 4 + h];
            acc += bs;
        }
        sc[h][jj] = acc;
    }
    __syncthreads();

    {   // softmax: warp w handles head w
        int w = tid >> 5, lane = tid & 31;
        float v0 = (lane < cnt) ? sc[w][lane] : -INFINITY;
        float v1 = (lane + 32 < cnt) ? sc[w][lane + 32] : -INFINITY;
        float mx = fmaxf(v0, v1);
#pragma unroll
        for (int o = 16; o; o >>= 1) mx = fmaxf(mx, __shfl_xor_sync(0xffffffffu, mx, o));
        float e0 = (lane < cnt) ? expf(v0 - mx) : 0.f;
        float e1 = (lane + 32 < cnt) ? expf(v1 - mx) : 0.f;
        float sm = e0 + e1;
#pragma unroll
        for (int o = 16; o; o >>= 1) sm += __shfl_xor_sync(0xffffffffu, sm, o);
        float inv = 1.f / sm;
        if (lane < cnt) sc[w][lane] = e0 * inv;
        if (lane + 32 < cnt) sc[w][lane + 32] = e1 * inv;
    }
    __syncthreads();

    {   // output: column tid (= h*32 + d)
        float o = 0.f;
        int h = tid >> 5;
        for (int jj = 0; jj < cnt; jj++) o += sc[h][jj] * Vb[jj][tid];
        attout[(size_t)i * DAA + tid] = o;
    }
}

// ---------------- elementwise epilogues ----------------
__global__ void epi1_kernel(const float* __restrict__ q, const float* __restrict__ QKVG,
                            const float* __restrict__ womul, const float* __restrict__ gates,
                            float* __restrict__ q1) {
    int idx = blockIdx.x * blockDim.x + threadIdx.x;
    if (idx >= NAA * DAA) return;
    int i = idx >> 7, c = idx & 127;
    float g = QKVG[(size_t)i * 512 + 384 + c];
    float sg = 1.f / (1.f + expf(-g));
    float v = q[idx] + sg * womul[idx];
    q1[idx] = v * (1.f + gates[(size_t)i * 256 + c]);
}

__global__ void swiglu_kernel(const float* __restrict__ ff, float* __restrict__ hid) {
    int idx = blockIdx.x * blockDim.x + threadIdx.x;
    if (idx >= NAA * 512) return;
    int i = idx >> 9, f = idx & 511;
    float a = ff[(size_t)i * 1024 + f];
    float b = ff[(size_t)i * 1024 + 512 + f];
    hid[idx] = (a / (1.f + expf(-a))) * b;
}

__global__ void final_kernel(const float* __restrict__ q1, const float* __restrict__ gates,
                             const float* __restrict__ swi, float* __restrict__ out) {
    int idx = blockIdx.x * blockDim.x + threadIdx.x;
    if (idx >= NAA * DAA) return;
    int i = idx >> 7, c = idx & 127;
    out[idx] = q1[idx] + gates[(size_t)i * 256 + 128 + c] * swi[idx];
}

// ---------------- launch ----------------
extern "C" void kernel_launch(void* const* d_in, const int* in_sizes, int n_in,
                              void* d_out, int out_size) {
    const float* q           = (const float*)d_in[0];
    const float* c_atom      = (const float*)d_in[1];
    const float* h_cond      = (const float*)d_in[2];
    const float* p_lm        = (const float*)d_in[3];
    const float* t_emb       = (const float*)d_in[4];
    const float* cond_proj_w = (const float*)d_in[5];
    const float* cond_proj_b = (const float*)d_in[6];
    const float* adaln1_w    = (const float*)d_in[7];
    const float* adaln1_b    = (const float*)d_in[8];
    const float* adaln2_w    = (const float*)d_in[9];
    const float* adaln2_b    = (const float*)d_in[10];
    const float* ln_g        = (const float*)d_in[11];
    const float* ln_b        = (const float*)d_in[12];
    const float* wq          = (const float*)d_in[13];
    const float* wk          = (const float*)d_in[14];
    const float* wv          = (const float*)d_in[15];
    const float* wg          = (const float*)d_in[16];
    const float* wo          = (const float*)d_in[17];
    const float* pair_w      = (const float*)d_in[18];
    const float* pair_b      = (const float*)d_in[19];
    const float* gate1_w     = (const float*)d_in[20];
    const float* gate1_b     = (const float*)d_in[21];
    const float* gate2_w     = (const float*)d_in[22];
    const float* gate2_b     = (const float*)d_in[23];
    const float* sw1         = (const float*)d_in[24];
    const float* sw3         = (const float*)d_in[25];
    const float* sw2         = (const float*)d_in[26];
    const int*   p_lm_idx    = (const int*)d_in[27];
    const int*   token_idx   = (const int*)d_in[28];
    float* out = (float*)d_out;

    float *cond, *ad, *qn, *qkvg, *gates, *attout, *womul, *q1, *qn2, *ff, *hid, *swi;
    float *Wqkvg, *Wad, *Bad, *Wg, *Bg, *Wff;
    int* bandp;
    cudaGetSymbolAddress((void**)&cond,   d_cond);
    cudaGetSymbolAddress((void**)&ad,     d_ad);
    cudaGetSymbolAddress((void**)&qn,     d_qn);
    cudaGetSymbolAddress((void**)&qkvg,   d_qkvg);
    cudaGetSymbolAddress((void**)&gates,  d_gates);
    cudaGetSymbolAddress((void**)&attout, d_attout);
    cudaGetSymbolAddress((void**)&womul,  d_womul);
    cudaGetSymbolAddress((void**)&q1,     d_q1);
    cudaGetSymbolAddress((void**)&qn2,    d_qn2);
    cudaGetSymbolAddress((void**)&ff,     d_ff);
    cudaGetSymbolAddress((void**)&hid,    d_hid);
    cudaGetSymbolAddress((void**)&swi,    d_swi);
    cudaGetSymbolAddress((void**)&bandp,  d_bandp);
    cudaGetSymbolAddress((void**)&Wqkvg,  d_Wqkvg);
    cudaGetSymbolAddress((void**)&Wad,    d_Wad);
    cudaGetSymbolAddress((void**)&Bad,    d_Bad);
    cudaGetSymbolAddress((void**)&Wg,     d_Wg);
    cudaGetSymbolAddress((void**)&Bg,     d_Bg);
    cudaGetSymbolAddress((void**)&Wff,    d_Wff);

    // pack weights
    pack_qkvg_kernel<<<64, 256>>>(wq, wk, wv, wg, Wqkvg);
    pack2_kernel<<<128, 256>>>(adaln1_w, adaln2_w, Wad, 128, 256);
    pack2_kernel<<<256, 256>>>(sw1, sw3, Wff, 128, 512);
    pack2_kernel<<<64, 256>>>(gate1_w, gate2_w, Wg, 128, 128);
    packv2_kernel<<<1, 256>>>(adaln1_b, adaln2_b, Bad, 256);
    packv2_kernel<<<1, 128>>>(gate1_b, gate2_b, Bg, 128);

    // cond = gather(h_cond) @ cond_proj_w + b + t_emb
    gemm_cond_kernel<<<dim3(2, 64), 256>>>(h_cond, token_idx, cond_proj_w, cond_proj_b, t_emb, cond);
    // adaln1|adaln2
    gemm_kernel<<<dim3(8, 64), 256>>>(cond, Wad, Bad, ad, NAA, 512, 128, 1);
    // q_n = (1+g1)*LN(q)*lng+lnb + b1
    ln_mod_kernel<<<512, 256>>>(q, ad, 0, ln_g, ln_b, qn);
    // QKVG
    gemm_kernel<<<dim3(8, 64), 256>>>(qn, Wqkvg, nullptr, qkvg, NAA, 512, 128, 0);
    // gates = sigmoid(c_atom @ [gate1|gate2] + b)
    gemm_kernel<<<dim3(4, 64), 256>>>(c_atom, Wg, Bg, gates, NAA, 256, 128, 2);
    // pair scatter
    band_init_kernel<<<(NAA * BAND + 255) / 256, 256>>>(bandp);
    scatter_pairs_kernel<<<PPP / 256, 256>>>(p_lm_idx, bandp);
    // banded attention
    attn_kernel<<<NAA, 128>>>(qkvg, bandp, p_lm, pair_w, pair_b, attout);
    // att_out @ wo
    gemm_kernel<<<dim3(2, 64), 256>>>(attout, wo, nullptr, womul, NAA, 128, 128, 0);
    // q1 = (q + sigmoid(G)*womul) * (1 + sig(gate1))
    epi1_kernel<<<2048, 256>>>(q, qkvg, womul, gates, q1);
    // q_n2 = (1+g2)*LN(q1) + b2
    ln_mod_kernel<<<512, 256>>>(q1, ad, 256, nullptr, nullptr, qn2);
    // [h1|h3] = qn2 @ [sw1|sw3]
    gemm_kernel<<<dim3(16, 64), 256>>>(qn2, Wff, nullptr, ff, NAA, 1024, 128, 0);
    // hid = silu(h1)*h3
    swiglu_kernel<<<8192, 256>>>(ff, hid);
    // swi = hid @ sw2
    gemm_kernel<<<dim3(2, 64), 256>>>(hid, sw2, nullptr, swi, NAA, 128, 512, 0);
    // out = q1 + sig(gate2)*swi
    final_kernel<<<2048, 256>>>(q1, gates, swi, out);
}